// round 5
// baseline (speedup 1.0000x reference)
#include <cuda_runtime.h>
#include <cuda_fp16.h>
#include <cuda_bf16.h>
#include <cstdint>

#define N_NODES 40000
#define N_EDGES 640000
#define D 128
#define BN_EPS 1e-5f

// padded K stride for SMEM tiles (bf16 elems): 136 -> bank-conflict-free frags
#define KP 136

// ---------------- device scratch (no allocations allowed) ----------------
__device__ __half g_h16[(size_t)N_NODES * D];     // f16 copy of h (gather messages)
__device__ float  g_hneigh[(size_t)N_NODES * D];  // mean-aggregated neighbors
__device__ float  g_y[(size_t)N_NODES * D];       // pre-batchnorm activations
__device__ int    g_cnt[N_NODES];
__device__ int    g_rowstart[N_NODES];
__device__ int    g_fill[N_NODES];
__device__ int    g_csr[N_EDGES];
__device__ float  g_colsum[D];
__device__ float  g_colsq[D];
// B = W^T stored [n][k] row-major, padded stride KP: [chunk][hi/lo][128*KP]
__device__ __align__(16) __nv_bfloat16 g_Bw[2][2][128 * KP];

// ---------------- K0: prep W^T hi/lo padded images ----------------
__global__ void __launch_bounds__(256) k_prepB(const float* __restrict__ Ws,
                                               const float* __restrict__ Wn) {
    int idx = blockIdx.x * 256 + threadIdx.x;          // 0..32767
    if (idx >= 2 * D * D) return;
    int chunk = idx >> 14;
    int n = (idx >> 7) & 127;                          // output col
    int k = idx & 127;                                 // K index
    float w = (chunk == 0 ? Ws : Wn)[k * D + n];
    __nv_bfloat16 hi = __float2bfloat16(w);
    __nv_bfloat16 lo = __float2bfloat16(w - __bfloat162float(hi));
    g_Bw[chunk][0][n * KP + k] = hi;
    g_Bw[chunk][1][n * KP + k] = lo;
}

// ---------------- K1: h -> f16, zero counters/stats ----------------
__global__ void __launch_bounds__(256) k_h16(const float* __restrict__ h) {
    int i = blockIdx.x * blockDim.x + threadIdx.x;
    if (i < N_NODES * (D / 4)) {
        float4 v = ((const float4*)h)[i];
        __half2 lo = __floats2half2_rn(v.x, v.y);
        __half2 hi = __floats2half2_rn(v.z, v.w);
        uint2 u;
        u.x = *(unsigned*)&lo;
        u.y = *(unsigned*)&hi;
        ((uint2*)g_h16)[i] = u;
    }
    if (i < N_NODES) g_cnt[i] = 0;
    if (i < D) { g_colsum[i] = 0.f; g_colsq[i] = 0.f; }
}

// ---------------- K2: degree histogram ----------------
__global__ void __launch_bounds__(256) k_hist(const int* __restrict__ dst) {
    int e = blockIdx.x * blockDim.x + threadIdx.x;
    if (e < N_EDGES) atomicAdd(&g_cnt[dst[e]], 1);
}

// ---------------- K3: fused single-block exclusive scan ----------------
__global__ void __launch_bounds__(1024) k_scan() {
    __shared__ int sh[1024];
    const int PER = (N_NODES + 1023) / 1024;           // 40
    int t = threadIdx.x;
    int base = t * PER;
    int lsum = 0;
    for (int i = 0; i < PER; i++) {
        int idx = base + i;
        if (idx < N_NODES) lsum += g_cnt[idx];
    }
    sh[t] = lsum;
    __syncthreads();
    for (int off = 1; off < 1024; off <<= 1) {
        int v = (t >= off) ? sh[t - off] : 0;
        __syncthreads();
        sh[t] += v;
        __syncthreads();
    }
    int pre = sh[t] - lsum;
    for (int i = 0; i < PER; i++) {
        int idx = base + i;
        if (idx < N_NODES) {
            int c = g_cnt[idx];
            g_rowstart[idx] = pre;
            g_fill[idx] = pre;
            pre += c;
        }
    }
}

// ---------------- K4: fill CSR ----------------
__global__ void __launch_bounds__(256) k_fill(const int* __restrict__ src,
                                              const int* __restrict__ dst) {
    int e = blockIdx.x * blockDim.x + threadIdx.x;
    if (e < N_EDGES) {
        int d = dst[e];
        int pos = atomicAdd(&g_fill[d], 1);
        g_csr[pos] = src[e];
    }
}

// ---------------- K5: warp-per-node gather (f16 msgs, fp32 accum) -------
__global__ void __launch_bounds__(256) k_gather() {
    int w = (blockIdx.x * 256 + threadIdx.x) >> 5;
    int lane = threadIdx.x & 31;
    if (w >= N_NODES) return;
    int rs  = g_rowstart[w];
    int deg = g_cnt[w];
    const uint2* hp = (const uint2*)g_h16;

    float4 acc = make_float4(0.f, 0.f, 0.f, 0.f);
    int j = 0;
    for (; j + 2 <= deg; j += 2) {
        int s0 = g_csr[rs + j];
        int s1 = g_csr[rs + j + 1];
        uint2 u0 = hp[(size_t)s0 * 32 + lane];
        uint2 u1 = hp[(size_t)s1 * 32 + lane];
        float2 a0 = __half22float2(*(__half2*)&u0.x);
        float2 a1 = __half22float2(*(__half2*)&u0.y);
        float2 b0 = __half22float2(*(__half2*)&u1.x);
        float2 b1 = __half22float2(*(__half2*)&u1.y);
        acc.x += a0.x + b0.x;  acc.y += a0.y + b0.y;
        acc.z += a1.x + b1.x;  acc.w += a1.y + b1.y;
    }
    if (j < deg) {
        int s0 = g_csr[rs + j];
        uint2 u0 = hp[(size_t)s0 * 32 + lane];
        float2 a0 = __half22float2(*(__half2*)&u0.x);
        float2 a1 = __half22float2(*(__half2*)&u0.y);
        acc.x += a0.x;  acc.y += a0.y;
        acc.z += a1.x;  acc.w += a1.y;
    }
    float inv = 1.0f / fmaxf((float)deg, 1.0f);
    float4 o;
    o.x = acc.x * inv; o.y = acc.y * inv; o.z = acc.z * inv; o.w = acc.w * inv;
    *(float4*)(g_hneigh + (size_t)w * D + lane * 4) = o;
}

// ---------------- K6: bf16-split HMMA GEMM + bias + relu + snorm --------
// y = relu([h | hneigh] @ [Ws; Wn] + b) * snorm -> g_y
// 256 threads = 8 warps; warp w -> rows [w*16, w*16+16); 128 rows/CTA.
// SMEM: Ahi | Alo | Bhi | Blo, each 128*KP bf16 = 34816 B. Total 139264 B.
#define ATILE (128 * KP)
#define SM_TOTAL (4 * ATILE * 2)

__device__ __forceinline__ void mma_bf16(float* c, uint32_t a0, uint32_t a1,
                                         uint32_t a2, uint32_t a3,
                                         uint32_t b0, uint32_t b1) {
    asm volatile(
        "mma.sync.aligned.m16n8k16.row.col.f32.bf16.bf16.f32 "
        "{%0,%1,%2,%3}, {%4,%5,%6,%7}, {%8,%9}, {%0,%1,%2,%3};"
        : "+f"(c[0]), "+f"(c[1]), "+f"(c[2]), "+f"(c[3])
        : "r"(a0), "r"(a1), "r"(a2), "r"(a3), "r"(b0), "r"(b1));
}

__global__ void __launch_bounds__(256) k_gemm_mma(const float* __restrict__ h,
                                                  const float* __restrict__ bias,
                                                  const float* __restrict__ snorm) {
    extern __shared__ __align__(16) __nv_bfloat16 smem[];
    __nv_bfloat16* Ahi = smem;
    __nv_bfloat16* Alo = smem + ATILE;
    __nv_bfloat16* Bhi = smem + 2 * ATILE;
    __nv_bfloat16* Blo = smem + 3 * ATILE;

    const int tid = threadIdx.x;
    const int w   = tid >> 5;
    const int lane = tid & 31;
    const int g = lane >> 2;       // group id (row within 8)
    const int t = lane & 3;        // thread in group (col pair)
    const int row0 = blockIdx.x * 128;

    // A staging mapping: thread -> (row r, 64-col half)
    const int r = tid >> 1;
    const int half = tid & 1;
    const int grow = row0 + r;
    const bool valid = (grow < N_NODES);

    float acc[16][4];
    #pragma unroll
    for (int nt = 0; nt < 16; nt++)
        #pragma unroll
        for (int c = 0; c < 4; c++) acc[nt][c] = 0.f;

    for (int chunk = 0; chunk < 2; chunk++) {
        __syncthreads();   // previous compute done before overwrite
        // ---- stage A: fp32 -> bf16 hi/lo ----
        {
            const float* srcp = chunk ? g_hneigh : h;
            const float4* rowp = (const float4*)(srcp + (size_t)grow * D) + half * 16;
            __nv_bfloat16* ah = Ahi + r * KP + half * 64;
            __nv_bfloat16* al = Alo + r * KP + half * 64;
            #pragma unroll
            for (int i = 0; i < 16; i++) {
                float4 v = valid ? rowp[i] : make_float4(0.f, 0.f, 0.f, 0.f);
                __nv_bfloat162 h0 = __floats2bfloat162_rn(v.x, v.y);
                __nv_bfloat162 h1 = __floats2bfloat162_rn(v.z, v.w);
                float2 f0 = __bfloat1622float2(h0);
                float2 f1 = __bfloat1622float2(h1);
                __nv_bfloat162 l0 = __floats2bfloat162_rn(v.x - f0.x, v.y - f0.y);
                __nv_bfloat162 l1 = __floats2bfloat162_rn(v.z - f1.x, v.w - f1.y);
                *(uint2*)(ah + i * 4) = make_uint2(*(uint32_t*)&h0, *(uint32_t*)&h1);
                *(uint2*)(al + i * 4) = make_uint2(*(uint32_t*)&l0, *(uint32_t*)&l1);
            }
        }
        // ---- copy B hi+lo (69632 B contiguous) ----
        {
            const uint4* bsrc = (const uint4*)&g_Bw[chunk][0][0];
            uint4* bdst = (uint4*)Bhi;
            #pragma unroll
            for (int i = 0; i < 17; i++) bdst[tid + i * 256] = bsrc[tid + i * 256];
        }
        __syncthreads();

        // ---- pass 1: (Ahi + Alo) x Bhi ----
        #pragma unroll
        for (int ks = 0; ks < 8; ks++) {
            const int k0 = ks * 16;
            const __nv_bfloat16* ar0 = Ahi + (w * 16 + g) * KP + k0 + t * 2;
            const __nv_bfloat16* ar1 = ar0 + 8 * KP;
            uint32_t ah0 = *(const uint32_t*)ar0;
            uint32_t ah2 = *(const uint32_t*)(ar0 + 8);
            uint32_t ah1 = *(const uint32_t*)ar1;
            uint32_t ah3 = *(const uint32_t*)(ar1 + 8);
            const __nv_bfloat16* al0p = Alo + (w * 16 + g) * KP + k0 + t * 2;
            const __nv_bfloat16* al1p = al0p + 8 * KP;
            uint32_t al0 = *(const uint32_t*)al0p;
            uint32_t al2 = *(const uint32_t*)(al0p + 8);
            uint32_t al1 = *(const uint32_t*)al1p;
            uint32_t al3 = *(const uint32_t*)(al1p + 8);
            #pragma unroll
            for (int nt = 0; nt < 16; nt++) {
                const __nv_bfloat16* br = Bhi + (nt * 8 + g) * KP + k0 + t * 2;
                uint32_t b0 = *(const uint32_t*)br;
                uint32_t b1 = *(const uint32_t*)(br + 8);
                mma_bf16(acc[nt], ah0, ah1, ah2, ah3, b0, b1);
                mma_bf16(acc[nt], al0, al1, al2, al3, b0, b1);
            }
        }
        // ---- pass 2: Ahi x Blo ----
        #pragma unroll
        for (int ks = 0; ks < 8; ks++) {
            const int k0 = ks * 16;
            const __nv_bfloat16* ar0 = Ahi + (w * 16 + g) * KP + k0 + t * 2;
            const __nv_bfloat16* ar1 = ar0 + 8 * KP;
            uint32_t ah0 = *(const uint32_t*)ar0;
            uint32_t ah2 = *(const uint32_t*)(ar0 + 8);
            uint32_t ah1 = *(const uint32_t*)ar1;
            uint32_t ah3 = *(const uint32_t*)(ar1 + 8);
            #pragma unroll
            for (int nt = 0; nt < 16; nt++) {
                const __nv_bfloat16* br = Blo + (nt * 8 + g) * KP + k0 + t * 2;
                uint32_t b0 = *(const uint32_t*)br;
                uint32_t b1 = *(const uint32_t*)(br + 8);
                mma_bf16(acc[nt], ah0, ah1, ah2, ah3, b0, b1);
            }
        }
    }

    // ---- epilogue: bias + relu + snorm -> g_y ----
    {
        int rowa = row0 + w * 16 + g;
        int rowb = rowa + 8;
        bool va = rowa < N_NODES;
        bool vb = rowb < N_NODES;
        float sna = va ? snorm[rowa] : 0.f;
        float snb = vb ? snorm[rowb] : 0.f;
        #pragma unroll
        for (int nt = 0; nt < 16; nt++) {
            int col = nt * 8 + t * 2;
            float b0 = bias[col], b1 = bias[col + 1];
            if (va) {
                float2 o;
                o.x = fmaxf(acc[nt][0] + b0, 0.f) * sna;
                o.y = fmaxf(acc[nt][1] + b1, 0.f) * sna;
                *(float2*)(g_y + (size_t)rowa * D + col) = o;
            }
            if (vb) {
                float2 o;
                o.x = fmaxf(acc[nt][2] + b0, 0.f) * snb;
                o.y = fmaxf(acc[nt][3] + b1, 0.f) * snb;
                *(float2*)(g_y + (size_t)rowb * D + col) = o;
            }
        }
    }
}

// ---------------- K7: column stats over g_y ----------------
__global__ void __launch_bounds__(256) k_stats() {
    __shared__ float red[8][D];
    int row0 = blockIdx.x * 128;
    int cx = threadIdx.x & 31;
    int rl = threadIdx.x >> 5;
    float4 s = make_float4(0.f, 0.f, 0.f, 0.f);
    float4 q = make_float4(0.f, 0.f, 0.f, 0.f);
    for (int j = rl; j < 128; j += 8) {
        int r = row0 + j;
        if (r < N_NODES) {
            float4 v = *(const float4*)(g_y + (size_t)r * D + cx * 4);
            s.x += v.x; s.y += v.y; s.z += v.z; s.w += v.w;
            q.x += v.x * v.x; q.y += v.y * v.y; q.z += v.z * v.z; q.w += v.w * v.w;
        }
    }
    *(float4*)&red[rl][cx * 4] = s;
    __syncthreads();
    if (threadIdx.x < D) {
        float tt = 0.f;
        #pragma unroll
        for (int r = 0; r < 8; r++) tt += red[r][threadIdx.x];
        atomicAdd(&g_colsum[threadIdx.x], tt);
    }
    __syncthreads();
    *(float4*)&red[rl][cx * 4] = q;
    __syncthreads();
    if (threadIdx.x < D) {
        float tt = 0.f;
        #pragma unroll
        for (int r = 0; r < 8; r++) tt += red[r][threadIdx.x];
        atomicAdd(&g_colsq[threadIdx.x], tt);
    }
}

// ---------------- K8: out = h + y*scale + shift (bn fused) ---------------
__global__ void __launch_bounds__(256) k_final(const float* __restrict__ h,
                                               const float* __restrict__ gamma,
                                               const float* __restrict__ beta,
                                               float* __restrict__ out) {
    __shared__ float ssc[D], ssh[D];
    if (threadIdx.x < D) {
        int c = threadIdx.x;
        float m  = g_colsum[c] * (1.0f / N_NODES);
        float va = g_colsq[c] * (1.0f / N_NODES) - m * m;
        float rs = rsqrtf(va + BN_EPS);
        float sc = rs * gamma[c];
        ssc[c] = sc;
        ssh[c] = beta[c] - m * sc;
    }
    __syncthreads();
    int i = blockIdx.x * blockDim.x + threadIdx.x;
    if (i >= N_NODES * (D / 4)) return;
    int c4 = i & (D / 4 - 1);
    float4 y  = ((const float4*)g_y)[i];
    float4 hh = ((const float4*)h)[i];
    float4 o;
    o.x = hh.x + y.x * ssc[c4 * 4 + 0] + ssh[c4 * 4 + 0];
    o.y = hh.y + y.y * ssc[c4 * 4 + 1] + ssh[c4 * 4 + 1];
    o.z = hh.z + y.z * ssc[c4 * 4 + 2] + ssh[c4 * 4 + 2];
    o.w = hh.w + y.w * ssc[c4 * 4 + 3] + ssh[c4 * 4 + 3];
    ((float4*)out)[i] = o;
}

// ---------------- launch ----------------
extern "C" void kernel_launch(void* const* d_in, const int* in_sizes, int n_in,
                              void* d_out, int out_size) {
    const float* h      = (const float*)d_in[0];
    const float* snorm  = (const float*)d_in[1];
    const float* Ws     = (const float*)d_in[2];
    const float* Wn     = (const float*)d_in[3];
    const float* bias   = (const float*)d_in[4];
    const float* gamma  = (const float*)d_in[5];
    const float* beta   = (const float*)d_in[6];
    const int*   src    = (const int*)d_in[7];
    const int*   dst    = (const int*)d_in[8];
    float* out = (float*)d_out;

    cudaFuncSetAttribute(k_gemm_mma, cudaFuncAttributeMaxDynamicSharedMemorySize,
                         SM_TOTAL);

    int nd4_blocks = (N_NODES * (D / 4) + 255) / 256;
    int edge_blocks = (N_EDGES + 255) / 256;
    int gemm_blocks = (N_NODES + 127) / 128;

    k_prepB<<<(2 * D * D + 255) / 256, 256>>>(Ws, Wn);
    k_h16<<<nd4_blocks, 256>>>(h);
    k_hist<<<edge_blocks, 256>>>(dst);
    k_scan<<<1, 1024>>>();
    k_fill<<<edge_blocks, 256>>>(src, dst);
    k_gather<<<(N_NODES * 32 + 255) / 256, 256>>>();
    k_gemm_mma<<<gemm_blocks, 256, SM_TOTAL>>>(h, bias, snorm);
    k_stats<<<gemm_blocks, 256>>>();
    k_final<<<nd4_blocks, 256>>>(h, gamma, beta, out);
}

// round 6
// speedup vs baseline: 1.4708x; 1.4708x over previous
#include <cuda_runtime.h>
#include <cuda_fp16.h>
#include <cuda_bf16.h>
#include <cstdint>

#define N_NODES 40000
#define N_EDGES 640000
#define D 128
#define BN_EPS 1e-5f

// padded K stride for SMEM tiles (bf16 elems): 136 -> bank-conflict-free frags
#define KP 136

// ---------------- device scratch (no allocations allowed) ----------------
__device__ __half g_h16[(size_t)N_NODES * D];     // f16 copy of h (gather messages)
__device__ float  g_hneigh[(size_t)N_NODES * D];  // mean-aggregated neighbors
__device__ float  g_y[(size_t)N_NODES * D];       // pre-batchnorm activations
__device__ int    g_cnt[N_NODES];
__device__ int    g_rowstart[N_NODES];
__device__ int    g_fill[N_NODES];
__device__ int    g_csr[N_EDGES];
__device__ int    g_total;
__device__ float  g_colsum[D];
__device__ float  g_colsq[D];
// B = W^T stored [n][k] row-major, padded stride KP: [chunk][hi/lo][128*KP]
__device__ __align__(16) __nv_bfloat16 g_Bw[2][2][128 * KP];

// ---------------- K0: prep W^T hi/lo padded images ----------------
__global__ void __launch_bounds__(256) k_prepB(const float* __restrict__ Ws,
                                               const float* __restrict__ Wn) {
    int idx = blockIdx.x * 256 + threadIdx.x;          // 0..32767
    if (idx >= 2 * D * D) return;
    int chunk = idx >> 14;
    int n = (idx >> 7) & 127;                          // output col
    int k = idx & 127;                                 // K index
    float w = (chunk == 0 ? Ws : Wn)[k * D + n];
    __nv_bfloat16 hi = __float2bfloat16(w);
    __nv_bfloat16 lo = __float2bfloat16(w - __bfloat162float(hi));
    g_Bw[chunk][0][n * KP + k] = hi;
    g_Bw[chunk][1][n * KP + k] = lo;
}

// ---------------- K1: h -> f16, zero counters/stats ----------------
__global__ void __launch_bounds__(256) k_h16(const float* __restrict__ h) {
    int i = blockIdx.x * blockDim.x + threadIdx.x;
    if (i < N_NODES * (D / 4)) {
        float4 v = ((const float4*)h)[i];
        __half2 lo = __floats2half2_rn(v.x, v.y);
        __half2 hi = __floats2half2_rn(v.z, v.w);
        uint2 u;
        u.x = *(unsigned*)&lo;
        u.y = *(unsigned*)&hi;
        ((uint2*)g_h16)[i] = u;
    }
    if (i < N_NODES) g_cnt[i] = 0;
    if (i < D) { g_colsum[i] = 0.f; g_colsq[i] = 0.f; }
    if (i == 0) g_total = 0;
}

// ---------------- K2: degree histogram ----------------
__global__ void __launch_bounds__(256) k_hist(const int* __restrict__ dst) {
    int e = blockIdx.x * blockDim.x + threadIdx.x;
    if (e < N_EDGES) atomicAdd(&g_cnt[dst[e]], 1);
}

// ---------------- K3: parallel scan; disjoint block bases via atomic ------
// CSR ranges need only be disjoint, not node-ordered, so each 256-node block
// scans locally and claims a base offset with one atomicAdd.
__global__ void __launch_bounds__(256) k_scan() {
    __shared__ int wsum[8];
    __shared__ int sbase;
    int i = blockIdx.x * 256 + threadIdx.x;
    int lane = threadIdx.x & 31;
    int wd = threadIdx.x >> 5;
    int c = (i < N_NODES) ? g_cnt[i] : 0;
    int v = c;
    #pragma unroll
    for (int off = 1; off < 32; off <<= 1) {
        int t = __shfl_up_sync(0xFFFFFFFF, v, off);
        if (lane >= off) v += t;
    }
    if (lane == 31) wsum[wd] = v;
    __syncthreads();
    if (threadIdx.x < 8) {
        int ws = wsum[threadIdx.x];
        int p = ws;
        #pragma unroll
        for (int off = 1; off < 8; off <<= 1) {
            int t = __shfl_up_sync(0xFF, p, off);
            if ((int)threadIdx.x >= off) p += t;
        }
        wsum[threadIdx.x] = p - ws;          // exclusive warp prefix
        if (threadIdx.x == 7) sbase = atomicAdd(&g_total, p);  // p = block total
    }
    __syncthreads();
    if (i < N_NODES) {
        int excl = sbase + wsum[wd] + v - c;
        g_rowstart[i] = excl;
        g_fill[i] = excl;
    }
}

// ---------------- K4: fill CSR ----------------
__global__ void __launch_bounds__(256) k_fill(const int* __restrict__ src,
                                              const int* __restrict__ dst) {
    int e = blockIdx.x * blockDim.x + threadIdx.x;
    if (e < N_EDGES) {
        int d = dst[e];
        int pos = atomicAdd(&g_fill[d], 1);
        g_csr[pos] = src[e];
    }
}

// ---------------- K5: warp-per-node gather (f16 msgs, fp32 accum) -------
__global__ void __launch_bounds__(256) k_gather() {
    int w = (blockIdx.x * 256 + threadIdx.x) >> 5;
    int lane = threadIdx.x & 31;
    if (w >= N_NODES) return;
    int rs  = g_rowstart[w];
    int deg = g_cnt[w];
    const uint2* hp = (const uint2*)g_h16;

    float4 acc = make_float4(0.f, 0.f, 0.f, 0.f);
    int j = 0;
    for (; j + 2 <= deg; j += 2) {
        int s0 = g_csr[rs + j];
        int s1 = g_csr[rs + j + 1];
        uint2 u0 = hp[(size_t)s0 * 32 + lane];
        uint2 u1 = hp[(size_t)s1 * 32 + lane];
        float2 a0 = __half22float2(*(__half2*)&u0.x);
        float2 a1 = __half22float2(*(__half2*)&u0.y);
        float2 b0 = __half22float2(*(__half2*)&u1.x);
        float2 b1 = __half22float2(*(__half2*)&u1.y);
        acc.x += a0.x + b0.x;  acc.y += a0.y + b0.y;
        acc.z += a1.x + b1.x;  acc.w += a1.y + b1.y;
    }
    if (j < deg) {
        int s0 = g_csr[rs + j];
        uint2 u0 = hp[(size_t)s0 * 32 + lane];
        float2 a0 = __half22float2(*(__half2*)&u0.x);
        float2 a1 = __half22float2(*(__half2*)&u0.y);
        acc.x += a0.x;  acc.y += a0.y;
        acc.z += a1.x;  acc.w += a1.y;
    }
    float inv = 1.0f / fmaxf((float)deg, 1.0f);
    float4 o;
    o.x = acc.x * inv; o.y = acc.y * inv; o.z = acc.z * inv; o.w = acc.w * inv;
    *(float4*)(g_hneigh + (size_t)w * D + lane * 4) = o;
}

// ---------------- K6: bf16-split HMMA GEMM + epilogue + col stats --------
// y = relu([h | hneigh] @ [Ws; Wn] + b) * snorm -> g_y ; stats fused.
#define ATILE (128 * KP)
#define SM_TOTAL (4 * ATILE * 2)

__device__ __forceinline__ void mma_bf16(float* c, uint32_t a0, uint32_t a1,
                                         uint32_t a2, uint32_t a3,
                                         uint32_t b0, uint32_t b1) {
    asm volatile(
        "mma.sync.aligned.m16n8k16.row.col.f32.bf16.bf16.f32 "
        "{%0,%1,%2,%3}, {%4,%5,%6,%7}, {%8,%9}, {%0,%1,%2,%3};"
        : "+f"(c[0]), "+f"(c[1]), "+f"(c[2]), "+f"(c[3])
        : "r"(a0), "r"(a1), "r"(a2), "r"(a3), "r"(b0), "r"(b1));
}

__global__ void __launch_bounds__(256) k_gemm_mma(const float* __restrict__ h,
                                                  const float* __restrict__ bias,
                                                  const float* __restrict__ snorm) {
    extern __shared__ __align__(16) __nv_bfloat16 smem[];
    __nv_bfloat16* Ahi = smem;
    __nv_bfloat16* Alo = smem + ATILE;
    __nv_bfloat16* Bhi = smem + 2 * ATILE;
    __nv_bfloat16* Blo = smem + 3 * ATILE;
    __shared__ float red[D];
    __shared__ float redq[D];

    const int tid = threadIdx.x;
    const int w   = tid >> 5;
    const int lane = tid & 31;
    const int g = lane >> 2;       // group id (row within 8)
    const int t = lane & 3;        // thread in group (col pair)
    const int row0 = blockIdx.x * 128;

    if (tid < D) { red[tid] = 0.f; redq[tid] = 0.f; }

    // A staging mapping: thread -> (row r, 64-col half)
    const int r = tid >> 1;
    const int half = tid & 1;
    const int grow = row0 + r;
    const bool valid = (grow < N_NODES);

    float acc[16][4];
    #pragma unroll
    for (int nt = 0; nt < 16; nt++)
        #pragma unroll
        for (int c = 0; c < 4; c++) acc[nt][c] = 0.f;

    for (int chunk = 0; chunk < 2; chunk++) {
        __syncthreads();   // previous compute done before overwrite
        // ---- stage A: fp32 -> bf16 hi/lo ----
        {
            const float* srcp = chunk ? g_hneigh : h;
            const float4* rowp = (const float4*)(srcp + (size_t)grow * D) + half * 16;
            __nv_bfloat16* ah = Ahi + r * KP + half * 64;
            __nv_bfloat16* al = Alo + r * KP + half * 64;
            #pragma unroll
            for (int i = 0; i < 16; i++) {
                float4 v = valid ? rowp[i] : make_float4(0.f, 0.f, 0.f, 0.f);
                __nv_bfloat162 h0 = __floats2bfloat162_rn(v.x, v.y);
                __nv_bfloat162 h1 = __floats2bfloat162_rn(v.z, v.w);
                float2 f0 = __bfloat1622float2(h0);
                float2 f1 = __bfloat1622float2(h1);
                __nv_bfloat162 l0 = __floats2bfloat162_rn(v.x - f0.x, v.y - f0.y);
                __nv_bfloat162 l1 = __floats2bfloat162_rn(v.z - f1.x, v.w - f1.y);
                *(uint2*)(ah + i * 4) = make_uint2(*(uint32_t*)&h0, *(uint32_t*)&h1);
                *(uint2*)(al + i * 4) = make_uint2(*(uint32_t*)&l0, *(uint32_t*)&l1);
            }
        }
        // ---- copy B hi+lo (69632 B contiguous) ----
        {
            const uint4* bsrc = (const uint4*)&g_Bw[chunk][0][0];
            uint4* bdst = (uint4*)Bhi;
            #pragma unroll
            for (int i = 0; i < 17; i++) bdst[tid + i * 256] = bsrc[tid + i * 256];
        }
        __syncthreads();

        // ---- pass 1: (Ahi + Alo) x Bhi ----
        #pragma unroll
        for (int ks = 0; ks < 8; ks++) {
            const int k0 = ks * 16;
            const __nv_bfloat16* ar0 = Ahi + (w * 16 + g) * KP + k0 + t * 2;
            const __nv_bfloat16* ar1 = ar0 + 8 * KP;
            uint32_t ah0 = *(const uint32_t*)ar0;
            uint32_t ah2 = *(const uint32_t*)(ar0 + 8);
            uint32_t ah1 = *(const uint32_t*)ar1;
            uint32_t ah3 = *(const uint32_t*)(ar1 + 8);
            const __nv_bfloat16* al0p = Alo + (w * 16 + g) * KP + k0 + t * 2;
            const __nv_bfloat16* al1p = al0p + 8 * KP;
            uint32_t al0 = *(const uint32_t*)al0p;
            uint32_t al2 = *(const uint32_t*)(al0p + 8);
            uint32_t al1 = *(const uint32_t*)al1p;
            uint32_t al3 = *(const uint32_t*)(al1p + 8);
            #pragma unroll
            for (int nt = 0; nt < 16; nt++) {
                const __nv_bfloat16* br = Bhi + (nt * 8 + g) * KP + k0 + t * 2;
                uint32_t b0 = *(const uint32_t*)br;
                uint32_t b1 = *(const uint32_t*)(br + 8);
                mma_bf16(acc[nt], ah0, ah1, ah2, ah3, b0, b1);
                mma_bf16(acc[nt], al0, al1, al2, al3, b0, b1);
            }
        }
        // ---- pass 2: Ahi x Blo ----
        #pragma unroll
        for (int ks = 0; ks < 8; ks++) {
            const int k0 = ks * 16;
            const __nv_bfloat16* ar0 = Ahi + (w * 16 + g) * KP + k0 + t * 2;
            const __nv_bfloat16* ar1 = ar0 + 8 * KP;
            uint32_t ah0 = *(const uint32_t*)ar0;
            uint32_t ah2 = *(const uint32_t*)(ar0 + 8);
            uint32_t ah1 = *(const uint32_t*)ar1;
            uint32_t ah3 = *(const uint32_t*)(ar1 + 8);
            #pragma unroll
            for (int nt = 0; nt < 16; nt++) {
                const __nv_bfloat16* br = Blo + (nt * 8 + g) * KP + k0 + t * 2;
                uint32_t b0 = *(const uint32_t*)br;
                uint32_t b1 = *(const uint32_t*)(br + 8);
                mma_bf16(acc[nt], ah0, ah1, ah2, ah3, b0, b1);
            }
        }
    }

    // ---- epilogue: bias + relu + snorm -> g_y ; fused column stats ----
    {
        int rowa = row0 + w * 16 + g;
        int rowb = rowa + 8;
        bool va = rowa < N_NODES;
        bool vb = rowb < N_NODES;
        float sna = va ? snorm[rowa] : 0.f;
        float snb = vb ? snorm[rowb] : 0.f;
        #pragma unroll
        for (int nt = 0; nt < 16; nt++) {
            int col = nt * 8 + t * 2;
            float b0 = bias[col], b1 = bias[col + 1];
            float2 oa, ob;
            oa.x = fmaxf(acc[nt][0] + b0, 0.f) * sna;
            oa.y = fmaxf(acc[nt][1] + b1, 0.f) * sna;
            ob.x = fmaxf(acc[nt][2] + b0, 0.f) * snb;
            ob.y = fmaxf(acc[nt][3] + b1, 0.f) * snb;
            if (va) *(float2*)(g_y + (size_t)rowa * D + col) = oa;
            if (vb) *(float2*)(g_y + (size_t)rowb * D + col) = ob;
            // per-thread 2-row sums, reduce over g (lanes stride 4)
            float s0 = oa.x + ob.x, s1 = oa.y + ob.y;
            float q0 = oa.x * oa.x + ob.x * ob.x, q1 = oa.y * oa.y + ob.y * ob.y;
            #pragma unroll
            for (int off = 16; off >= 4; off >>= 1) {
                s0 += __shfl_down_sync(0xFFFFFFFF, s0, off);
                s1 += __shfl_down_sync(0xFFFFFFFF, s1, off);
                q0 += __shfl_down_sync(0xFFFFFFFF, q0, off);
                q1 += __shfl_down_sync(0xFFFFFFFF, q1, off);
            }
            if (g == 0) {
                atomicAdd(&red[col], s0);
                atomicAdd(&red[col + 1], s1);
                atomicAdd(&redq[col], q0);
                atomicAdd(&redq[col + 1], q1);
            }
        }
    }
    __syncthreads();
    if (tid < D) {
        atomicAdd(&g_colsum[tid], red[tid]);
        atomicAdd(&g_colsq[tid], redq[tid]);
    }
}

// ---------------- K7: out = h + y*scale + shift (bn fused) ---------------
__global__ void __launch_bounds__(256) k_final(const float* __restrict__ h,
                                               const float* __restrict__ gamma,
                                               const float* __restrict__ beta,
                                               float* __restrict__ out) {
    __shared__ float ssc[D], ssh[D];
    if (threadIdx.x < D) {
        int c = threadIdx.x;
        float m  = g_colsum[c] * (1.0f / N_NODES);
        float va = g_colsq[c] * (1.0f / N_NODES) - m * m;
        float rs = rsqrtf(va + BN_EPS);
        float sc = rs * gamma[c];
        ssc[c] = sc;
        ssh[c] = beta[c] - m * sc;
    }
    __syncthreads();
    int i = blockIdx.x * blockDim.x + threadIdx.x;
    if (i >= N_NODES * (D / 4)) return;
    int c4 = i & (D / 4 - 1);
    float4 y  = ((const float4*)g_y)[i];
    float4 hh = ((const float4*)h)[i];
    float4 o;
    o.x = hh.x + y.x * ssc[c4 * 4 + 0] + ssh[c4 * 4 + 0];
    o.y = hh.y + y.y * ssc[c4 * 4 + 1] + ssh[c4 * 4 + 1];
    o.z = hh.z + y.z * ssc[c4 * 4 + 2] + ssh[c4 * 4 + 2];
    o.w = hh.w + y.w * ssc[c4 * 4 + 3] + ssh[c4 * 4 + 3];
    ((float4*)out)[i] = o;
}

// ---------------- launch ----------------
extern "C" void kernel_launch(void* const* d_in, const int* in_sizes, int n_in,
                              void* d_out, int out_size) {
    const float* h      = (const float*)d_in[0];
    const float* snorm  = (const float*)d_in[1];
    const float* Ws     = (const float*)d_in[2];
    const float* Wn     = (const float*)d_in[3];
    const float* bias   = (const float*)d_in[4];
    const float* gamma  = (const float*)d_in[5];
    const float* beta   = (const float*)d_in[6];
    const int*   src    = (const int*)d_in[7];
    const int*   dst    = (const int*)d_in[8];
    float* out = (float*)d_out;

    cudaFuncSetAttribute(k_gemm_mma, cudaFuncAttributeMaxDynamicSharedMemorySize,
                         SM_TOTAL);

    int nd4_blocks = (N_NODES * (D / 4) + 255) / 256;
    int edge_blocks = (N_EDGES + 255) / 256;
    int gemm_blocks = (N_NODES + 127) / 128;
    int node_blocks = (N_NODES + 255) / 256;

    k_prepB<<<(2 * D * D + 255) / 256, 256>>>(Ws, Wn);
    k_h16<<<nd4_blocks, 256>>>(h);
    k_hist<<<edge_blocks, 256>>>(dst);
    k_scan<<<node_blocks, 256>>>();
    k_fill<<<edge_blocks, 256>>>(src, dst);
    k_gather<<<(N_NODES * 32 + 255) / 256, 256>>>();
    k_gemm_mma<<<gemm_blocks, 256, SM_TOTAL>>>(h, bias, snorm);
    k_final<<<nd4_blocks, 256>>>(h, gamma, beta, out);
}

// round 7
// speedup vs baseline: 1.5243x; 1.0363x over previous
#include <cuda_runtime.h>
#include <cuda_fp16.h>
#include <cuda_bf16.h>
#include <cstdint>

#define N_NODES 40000
#define N_EDGES 640000
#define D 128
#define BN_EPS 1e-5f
#define KP 136   // padded K stride (bf16) -> conflict-free MMA frags

// ---------------- device scratch (no allocations allowed) ----------------
__device__ __half g_h16[(size_t)N_NODES * D];     // f16 copy of h
__device__ __half g_hn16[(size_t)N_NODES * D];    // f16 mean-aggregated neighbors
__device__ float  g_y[(size_t)N_NODES * D];       // pre-batchnorm activations
__device__ int    g_cnt[N_NODES];                 // zero-init; re-zeroed by k_final
__device__ int    g_rowstart[N_NODES];
__device__ int    g_fill[N_NODES];
__device__ int    g_csr[N_EDGES];
__device__ int    g_total;
__device__ float  g_colsum[D];
__device__ float  g_colsq[D];
__device__ __align__(16) __nv_bfloat16 g_Bw[2][2][128 * KP];

// ---------------- K1: fused prep: h->f16, hist, W split, zero stats ------
__global__ void __launch_bounds__(256) k_prep(const float* __restrict__ h,
                                              const int* __restrict__ dst,
                                              const float* __restrict__ Ws,
                                              const float* __restrict__ Wn) {
    int i = blockIdx.x * 256 + threadIdx.x;
    if (i < N_NODES * (D / 4)) {               // h -> f16
        float4 v = ((const float4*)h)[i];
        __half2 lo = __floats2half2_rn(v.x, v.y);
        __half2 hi = __floats2half2_rn(v.z, v.w);
        ((uint2*)g_h16)[i] = make_uint2(*(unsigned*)&lo, *(unsigned*)&hi);
    }
    if (i < N_EDGES) atomicAdd(&g_cnt[dst[i]], 1);   // cnt pre-zeroed (init/k_final)
    if (i < 2 * D * D) {                       // W^T hi/lo split images
        int chunk = i >> 14;
        int n = (i >> 7) & 127;
        int k = i & 127;
        float w = (chunk == 0 ? Ws : Wn)[k * D + n];
        __nv_bfloat16 hi = __float2bfloat16(w);
        __nv_bfloat16 lo = __float2bfloat16(w - __bfloat162float(hi));
        g_Bw[chunk][0][n * KP + k] = hi;
        g_Bw[chunk][1][n * KP + k] = lo;
    }
    if (i < D) { g_colsum[i] = 0.f; g_colsq[i] = 0.f; }
    if (i == 0) g_total = 0;
}

// ---------------- K2: scan; disjoint block bases via atomic --------------
__global__ void __launch_bounds__(256) k_scan() {
    __shared__ int wsum[8];
    __shared__ int sbase;
    int i = blockIdx.x * 256 + threadIdx.x;
    int lane = threadIdx.x & 31;
    int wd = threadIdx.x >> 5;
    int c = (i < N_NODES) ? g_cnt[i] : 0;
    int v = c;
    #pragma unroll
    for (int off = 1; off < 32; off <<= 1) {
        int t = __shfl_up_sync(0xFFFFFFFF, v, off);
        if (lane >= off) v += t;
    }
    if (lane == 31) wsum[wd] = v;
    __syncthreads();
    if (threadIdx.x < 8) {
        int ws = wsum[threadIdx.x];
        int p = ws;
        #pragma unroll
        for (int off = 1; off < 8; off <<= 1) {
            int t = __shfl_up_sync(0xFF, p, off);
            if ((int)threadIdx.x >= off) p += t;
        }
        wsum[threadIdx.x] = p - ws;
        if (threadIdx.x == 7) sbase = atomicAdd(&g_total, p);
    }
    __syncthreads();
    if (i < N_NODES) {
        int excl = sbase + wsum[wd] + v - c;
        g_rowstart[i] = excl;
        g_fill[i] = excl;
    }
}

// ---------------- K3: fill CSR ----------------
__global__ void __launch_bounds__(256) k_fill(const int* __restrict__ src,
                                              const int* __restrict__ dst) {
    int e = blockIdx.x * blockDim.x + threadIdx.x;
    if (e < N_EDGES) {
        int d = dst[e];
        int pos = atomicAdd(&g_fill[d], 1);
        g_csr[pos] = src[e];
    }
}

// ---------------- K4: warp-per-node gather, 16B lanes, MLP=2 -------------
__device__ __forceinline__ void add8(float* a, uint4 u) {
    float2 f;
    f = __half22float2(*(__half2*)&u.x); a[0] += f.x; a[1] += f.y;
    f = __half22float2(*(__half2*)&u.y); a[2] += f.x; a[3] += f.y;
    f = __half22float2(*(__half2*)&u.z); a[4] += f.x; a[5] += f.y;
    f = __half22float2(*(__half2*)&u.w); a[6] += f.x; a[7] += f.y;
}
__global__ void __launch_bounds__(256) k_gather() {
    int w = (blockIdx.x * 256 + threadIdx.x) >> 5;
    int lane = threadIdx.x & 31;
    if (w >= N_NODES) return;
    int rs  = g_rowstart[w];
    int deg = g_cnt[w];
    int hl = lane >> 4;            // half-group: neighbor parity
    int li = lane & 15;            // 16 lanes x uint4 = one 128-half row
    const uint4* hp = (const uint4*)g_h16;

    float acc[8] = {0.f, 0.f, 0.f, 0.f, 0.f, 0.f, 0.f, 0.f};
    int j = 0;
    for (; j + 4 <= deg; j += 4) {
        int sA = g_csr[rs + j + hl];
        int sB = g_csr[rs + j + 2 + hl];
        uint4 uA = hp[(size_t)sA * 16 + li];
        uint4 uB = hp[(size_t)sB * 16 + li];
        add8(acc, uA);
        add8(acc, uB);
    }
    for (; j + 2 <= deg; j += 2) {
        int sA = g_csr[rs + j + hl];
        add8(acc, hp[(size_t)sA * 16 + li]);
    }
    if (j < deg && hl == 0) {
        int sA = g_csr[rs + j];
        add8(acc, hp[(size_t)sA * 16 + li]);
    }
    #pragma unroll
    for (int k = 0; k < 8; k++)
        acc[k] += __shfl_down_sync(0xFFFFFFFF, acc[k], 16);
    if (hl == 0) {
        float inv = 1.0f / fmaxf((float)deg, 1.0f);
        __half2 o0 = __floats2half2_rn(acc[0] * inv, acc[1] * inv);
        __half2 o1 = __floats2half2_rn(acc[2] * inv, acc[3] * inv);
        __half2 o2 = __floats2half2_rn(acc[4] * inv, acc[5] * inv);
        __half2 o3 = __floats2half2_rn(acc[6] * inv, acc[7] * inv);
        uint4 o = make_uint4(*(unsigned*)&o0, *(unsigned*)&o1,
                             *(unsigned*)&o2, *(unsigned*)&o3);
        ((uint4*)g_hn16)[(size_t)w * 16 + li] = o;
    }
}

// ---------------- K5: bf16-split HMMA GEMM + epilogue + col stats --------
#define ATILE (128 * KP)
#define SM_TOTAL (4 * ATILE * 2)

__device__ __forceinline__ void mma_bf16(float* c, uint32_t a0, uint32_t a1,
                                         uint32_t a2, uint32_t a3,
                                         uint32_t b0, uint32_t b1) {
    asm volatile(
        "mma.sync.aligned.m16n8k16.row.col.f32.bf16.bf16.f32 "
        "{%0,%1,%2,%3}, {%4,%5,%6,%7}, {%8,%9}, {%0,%1,%2,%3};"
        : "+f"(c[0]), "+f"(c[1]), "+f"(c[2]), "+f"(c[3])
        : "r"(a0), "r"(a1), "r"(a2), "r"(a3), "r"(b0), "r"(b1));
}

__global__ void __launch_bounds__(256) k_gemm_mma(const float* __restrict__ h,
                                                  const float* __restrict__ bias,
                                                  const float* __restrict__ snorm) {
    extern __shared__ __align__(16) __nv_bfloat16 smem[];
    __nv_bfloat16* Ahi = smem;
    __nv_bfloat16* Alo = smem + ATILE;
    __nv_bfloat16* Bhi = smem + 2 * ATILE;
    __nv_bfloat16* Blo = smem + 3 * ATILE;
    __shared__ float red[D];
    __shared__ float redq[D];

    const int tid = threadIdx.x;
    const int w   = tid >> 5;
    const int lane = tid & 31;
    const int g = lane >> 2;
    const int t = lane & 3;
    const int row0 = blockIdx.x * 128;

    if (tid < D) { red[tid] = 0.f; redq[tid] = 0.f; }

    const int r = tid >> 1;
    const int half = tid & 1;
    const int grow = row0 + r;
    const bool valid = (grow < N_NODES);

    float acc[16][4];
    #pragma unroll
    for (int nt = 0; nt < 16; nt++)
        #pragma unroll
        for (int c = 0; c < 4; c++) acc[nt][c] = 0.f;

    for (int chunk = 0; chunk < 2; chunk++) {
        __syncthreads();
        // ---- stage A: hi/lo bf16 split ----
        {
            __nv_bfloat16* ah = Ahi + r * KP + half * 64;
            __nv_bfloat16* al = Alo + r * KP + half * 64;
            const float4* rowp = (const float4*)(h + (size_t)grow * D) + half * 16;
            const uint2* rp16 = (const uint2*)(g_hn16 + (size_t)grow * D) + half * 16;
            #pragma unroll
            for (int i = 0; i < 16; i++) {
                float4 v;
                if (chunk == 0) {
                    v = valid ? rowp[i] : make_float4(0.f, 0.f, 0.f, 0.f);
                } else {
                    uint2 u = valid ? rp16[i] : make_uint2(0, 0);
                    float2 f0 = __half22float2(*(__half2*)&u.x);
                    float2 f1 = __half22float2(*(__half2*)&u.y);
                    v = make_float4(f0.x, f0.y, f1.x, f1.y);
                }
                __nv_bfloat162 h0 = __floats2bfloat162_rn(v.x, v.y);
                __nv_bfloat162 h1 = __floats2bfloat162_rn(v.z, v.w);
                float2 f0 = __bfloat1622float2(h0);
                float2 f1 = __bfloat1622float2(h1);
                __nv_bfloat162 l0 = __floats2bfloat162_rn(v.x - f0.x, v.y - f0.y);
                __nv_bfloat162 l1 = __floats2bfloat162_rn(v.z - f1.x, v.w - f1.y);
                *(uint2*)(ah + i * 4) = make_uint2(*(uint32_t*)&h0, *(uint32_t*)&h1);
                *(uint2*)(al + i * 4) = make_uint2(*(uint32_t*)&l0, *(uint32_t*)&l1);
            }
        }
        // ---- copy B hi+lo ----
        {
            const uint4* bsrc = (const uint4*)&g_Bw[chunk][0][0];
            uint4* bdst = (uint4*)Bhi;
            #pragma unroll
            for (int i = 0; i < 17; i++) bdst[tid + i * 256] = bsrc[tid + i * 256];
        }
        __syncthreads();

        // ---- pass 1: (Ahi + Alo) x Bhi ----
        #pragma unroll
        for (int ks = 0; ks < 8; ks++) {
            const int k0 = ks * 16;
            const __nv_bfloat16* ar0 = Ahi + (w * 16 + g) * KP + k0 + t * 2;
            const __nv_bfloat16* ar1 = ar0 + 8 * KP;
            uint32_t ah0 = *(const uint32_t*)ar0;
            uint32_t ah2 = *(const uint32_t*)(ar0 + 8);
            uint32_t ah1 = *(const uint32_t*)ar1;
            uint32_t ah3 = *(const uint32_t*)(ar1 + 8);
            const __nv_bfloat16* al0p = Alo + (w * 16 + g) * KP + k0 + t * 2;
            const __nv_bfloat16* al1p = al0p + 8 * KP;
            uint32_t al0 = *(const uint32_t*)al0p;
            uint32_t al2 = *(const uint32_t*)(al0p + 8);
            uint32_t al1 = *(const uint32_t*)al1p;
            uint32_t al3 = *(const uint32_t*)(al1p + 8);
            #pragma unroll
            for (int nt = 0; nt < 16; nt++) {
                const __nv_bfloat16* br = Bhi + (nt * 8 + g) * KP + k0 + t * 2;
                uint32_t b0 = *(const uint32_t*)br;
                uint32_t b1 = *(const uint32_t*)(br + 8);
                mma_bf16(acc[nt], ah0, ah1, ah2, ah3, b0, b1);
                mma_bf16(acc[nt], al0, al1, al2, al3, b0, b1);
            }
        }
        // ---- pass 2: Ahi x Blo ----
        #pragma unroll
        for (int ks = 0; ks < 8; ks++) {
            const int k0 = ks * 16;
            const __nv_bfloat16* ar0 = Ahi + (w * 16 + g) * KP + k0 + t * 2;
            const __nv_bfloat16* ar1 = ar0 + 8 * KP;
            uint32_t ah0 = *(const uint32_t*)ar0;
            uint32_t ah2 = *(const uint32_t*)(ar0 + 8);
            uint32_t ah1 = *(const uint32_t*)ar1;
            uint32_t ah3 = *(const uint32_t*)(ar1 + 8);
            #pragma unroll
            for (int nt = 0; nt < 16; nt++) {
                const __nv_bfloat16* br = Blo + (nt * 8 + g) * KP + k0 + t * 2;
                uint32_t b0 = *(const uint32_t*)br;
                uint32_t b1 = *(const uint32_t*)(br + 8);
                mma_bf16(acc[nt], ah0, ah1, ah2, ah3, b0, b1);
            }
        }
    }

    // ---- epilogue: bias + relu + snorm -> g_y ; fused column stats ----
    {
        int rowa = row0 + w * 16 + g;
        int rowb = rowa + 8;
        bool va = rowa < N_NODES;
        bool vb = rowb < N_NODES;
        float sna = va ? snorm[rowa] : 0.f;
        float snb = vb ? snorm[rowb] : 0.f;
        #pragma unroll
        for (int nt = 0; nt < 16; nt++) {
            int col = nt * 8 + t * 2;
            float b0 = bias[col], b1 = bias[col + 1];
            float2 oa, ob;
            oa.x = fmaxf(acc[nt][0] + b0, 0.f) * sna;
            oa.y = fmaxf(acc[nt][1] + b1, 0.f) * sna;
            ob.x = fmaxf(acc[nt][2] + b0, 0.f) * snb;
            ob.y = fmaxf(acc[nt][3] + b1, 0.f) * snb;
            if (va) *(float2*)(g_y + (size_t)rowa * D + col) = oa;
            if (vb) *(float2*)(g_y + (size_t)rowb * D + col) = ob;
            float s0 = oa.x + ob.x, s1 = oa.y + ob.y;
            float q0 = oa.x * oa.x + ob.x * ob.x, q1 = oa.y * oa.y + ob.y * ob.y;
            #pragma unroll
            for (int off = 16; off >= 4; off >>= 1) {
                s0 += __shfl_down_sync(0xFFFFFFFF, s0, off);
                s1 += __shfl_down_sync(0xFFFFFFFF, s1, off);
                q0 += __shfl_down_sync(0xFFFFFFFF, q0, off);
                q1 += __shfl_down_sync(0xFFFFFFFF, q1, off);
            }
            if (g == 0) {
                atomicAdd(&red[col], s0);
                atomicAdd(&red[col + 1], s1);
                atomicAdd(&redq[col], q0);
                atomicAdd(&redq[col + 1], q1);
            }
        }
    }
    __syncthreads();
    if (tid < D) {
        atomicAdd(&g_colsum[tid], red[tid]);
        atomicAdd(&g_colsq[tid], redq[tid]);
    }
}

// ---------------- K6: out = h + y*scale + shift ; re-zero g_cnt ----------
__global__ void __launch_bounds__(256) k_final(const float* __restrict__ h,
                                               const float* __restrict__ gamma,
                                               const float* __restrict__ beta,
                                               float* __restrict__ out) {
    __shared__ float ssc[D], ssh[D];
    if (threadIdx.x < D) {
        int c = threadIdx.x;
        float m  = g_colsum[c] * (1.0f / N_NODES);
        float va = g_colsq[c] * (1.0f / N_NODES) - m * m;
        float rs = rsqrtf(va + BN_EPS);
        float sc = rs * gamma[c];
        ssc[c] = sc;
        ssh[c] = beta[c] - m * sc;
    }
    __syncthreads();
    int i = blockIdx.x * blockDim.x + threadIdx.x;
    if (i < N_NODES) g_cnt[i] = 0;     // invariant: cnt zeroed for next run
    if (i >= N_NODES * (D / 4)) return;
    int c4 = i & (D / 4 - 1);
    float4 y  = ((const float4*)g_y)[i];
    float4 hh = ((const float4*)h)[i];
    float4 o;
    o.x = hh.x + y.x * ssc[c4 * 4 + 0] + ssh[c4 * 4 + 0];
    o.y = hh.y + y.y * ssc[c4 * 4 + 1] + ssh[c4 * 4 + 1];
    o.z = hh.z + y.z * ssc[c4 * 4 + 2] + ssh[c4 * 4 + 2];
    o.w = hh.w + y.w * ssc[c4 * 4 + 3] + ssh[c4 * 4 + 3];
    ((float4*)out)[i] = o;
}

// ---------------- launch ----------------
extern "C" void kernel_launch(void* const* d_in, const int* in_sizes, int n_in,
                              void* d_out, int out_size) {
    const float* h      = (const float*)d_in[0];
    const float* snorm  = (const float*)d_in[1];
    const float* Ws     = (const float*)d_in[2];
    const float* Wn     = (const float*)d_in[3];
    const float* bias   = (const float*)d_in[4];
    const float* gamma  = (const float*)d_in[5];
    const float* beta   = (const float*)d_in[6];
    const int*   src    = (const int*)d_in[7];
    const int*   dst    = (const int*)d_in[8];
    float* out = (float*)d_out;

    cudaFuncSetAttribute(k_gemm_mma, cudaFuncAttributeMaxDynamicSharedMemorySize,
                         SM_TOTAL);

    int nd4_blocks = (N_NODES * (D / 4) + 255) / 256;   // 5000
    int edge_blocks = (N_EDGES + 255) / 256;            // 2500
    int gemm_blocks = (N_NODES + 127) / 128;            // 313
    int node_blocks = (N_NODES + 255) / 256;            // 157

    k_prep<<<nd4_blocks, 256>>>(h, dst, Ws, Wn);
    k_scan<<<node_blocks, 256>>>();
    k_fill<<<edge_blocks, 256>>>(src, dst);
    k_gather<<<(N_NODES * 32 + 255) / 256, 256>>>();
    k_gemm_mma<<<gemm_blocks, 256, SM_TOTAL>>>(h, bias, snorm);
    k_final<<<nd4_blocks, 256>>>(h, gamma, beta, out);
}

// round 8
// speedup vs baseline: 1.5276x; 1.0022x over previous
#include <cuda_runtime.h>
#include <cuda_fp16.h>
#include <cuda_bf16.h>
#include <cstdint>

#define N_NODES 40000
#define N_EDGES 640000
#define D 128
#define BN_EPS 1e-5f
#define KP 136   // padded K stride (bf16) -> conflict-free MMA frags

// ---------------- device scratch (no allocations allowed) ----------------
__device__ __half g_h16[(size_t)N_NODES * D];     // f16 copy of h
__device__ __half g_hn16[(size_t)N_NODES * D];    // f16 mean-aggregated neighbors
__device__ float  g_y[(size_t)N_NODES * D];       // pre-batchnorm activations
__device__ int    g_cnt[N_NODES];                 // zero-init; re-zeroed by k_final
__device__ int    g_rowstart[N_NODES];
__device__ int    g_fill[N_NODES];
__device__ int    g_csr[N_EDGES];
__device__ int    g_total;
__device__ float  g_colsum[D];
__device__ float  g_colsq[D];
__device__ __align__(16) __nv_bfloat16 g_Bw[2][2][128 * KP];

// ---------------- K1: fused prep: h->f16, hist, W split, zero stats ------
__global__ void __launch_bounds__(256) k_prep(const float* __restrict__ h,
                                              const int* __restrict__ dst,
                                              const float* __restrict__ Ws,
                                              const float* __restrict__ Wn) {
    int i = blockIdx.x * 256 + threadIdx.x;
    if (i < N_NODES * (D / 4)) {               // h -> f16
        float4 v = ((const float4*)h)[i];
        __half2 lo = __floats2half2_rn(v.x, v.y);
        __half2 hi = __floats2half2_rn(v.z, v.w);
        ((uint2*)g_h16)[i] = make_uint2(*(unsigned*)&lo, *(unsigned*)&hi);
    }
    if (i < N_EDGES) atomicAdd(&g_cnt[dst[i]], 1);   // cnt pre-zeroed (init/k_final)
    if (i < 2 * D * D) {                       // W^T hi/lo split images
        int chunk = i >> 14;
        int n = (i >> 7) & 127;
        int k = i & 127;
        float w = (chunk == 0 ? Ws : Wn)[k * D + n];
        __nv_bfloat16 hi = __float2bfloat16(w);
        __nv_bfloat16 lo = __float2bfloat16(w - __bfloat162float(hi));
        g_Bw[chunk][0][n * KP + k] = hi;
        g_Bw[chunk][1][n * KP + k] = lo;
    }
    if (i < D) { g_colsum[i] = 0.f; g_colsq[i] = 0.f; }
    if (i == 0) g_total = 0;
}

// ---------------- K2: scan; disjoint block bases via atomic --------------
__global__ void __launch_bounds__(256) k_scan() {
    __shared__ int wsum[8];
    __shared__ int sbase;
    int i = blockIdx.x * 256 + threadIdx.x;
    int lane = threadIdx.x & 31;
    int wd = threadIdx.x >> 5;
    int c = (i < N_NODES) ? g_cnt[i] : 0;
    int v = c;
    #pragma unroll
    for (int off = 1; off < 32; off <<= 1) {
        int t = __shfl_up_sync(0xFFFFFFFF, v, off);
        if (lane >= off) v += t;
    }
    if (lane == 31) wsum[wd] = v;
    __syncthreads();
    if (threadIdx.x < 8) {
        int ws = wsum[threadIdx.x];
        int p = ws;
        #pragma unroll
        for (int off = 1; off < 8; off <<= 1) {
            int t = __shfl_up_sync(0xFF, p, off);
            if ((int)threadIdx.x >= off) p += t;
        }
        wsum[threadIdx.x] = p - ws;
        if (threadIdx.x == 7) sbase = atomicAdd(&g_total, p);
    }
    __syncthreads();
    if (i < N_NODES) {
        int excl = sbase + wsum[wd] + v - c;
        g_rowstart[i] = excl;
        g_fill[i] = excl;
    }
}

// ---------------- K3: fill CSR ----------------
__global__ void __launch_bounds__(256) k_fill(const int* __restrict__ src,
                                              const int* __restrict__ dst) {
    int e = blockIdx.x * blockDim.x + threadIdx.x;
    if (e < N_EDGES) {
        int d = dst[e];
        int pos = atomicAdd(&g_fill[d], 1);
        g_csr[pos] = src[e];
    }
}

// ---------------- K4: warp-per-node gather, fp16 pairwise + fp32 accum ---
__device__ __forceinline__ void add8f(float* a, uint4 u) {
    float2 f;
    f = __half22float2(*(__half2*)&u.x); a[0] += f.x; a[1] += f.y;
    f = __half22float2(*(__half2*)&u.y); a[2] += f.x; a[3] += f.y;
    f = __half22float2(*(__half2*)&u.z); a[4] += f.x; a[5] += f.y;
    f = __half22float2(*(__half2*)&u.w); a[6] += f.x; a[7] += f.y;
}
__global__ void __launch_bounds__(256) k_gather() {
    int w = (blockIdx.x * 256 + threadIdx.x) >> 5;
    int lane = threadIdx.x & 31;
    if (w >= N_NODES) return;
    int rs  = g_rowstart[w];
    int deg = g_cnt[w];
    int hl = lane >> 4;            // half-group: neighbor parity
    int li = lane & 15;            // 16 lanes x uint4 = one 128-half row
    const uint4* hp = (const uint4*)g_h16;

    float acc[8] = {0.f, 0.f, 0.f, 0.f, 0.f, 0.f, 0.f, 0.f};
    int j = 0;
    // main loop: 4 edges/iter; pair the two loads in fp16 (HADD2) before
    // converting -> halves the cvt+fadd instruction stream (issue-bound fix).
    for (; j + 4 <= deg; j += 4) {
        int sA = g_csr[rs + j + hl];
        int sB = g_csr[rs + j + 2 + hl];
        uint4 uA = hp[(size_t)sA * 16 + li];
        uint4 uB = hp[(size_t)sB * 16 + li];
        __half2 p0 = __hadd2(*(__half2*)&uA.x, *(__half2*)&uB.x);
        __half2 p1 = __hadd2(*(__half2*)&uA.y, *(__half2*)&uB.y);
        __half2 p2 = __hadd2(*(__half2*)&uA.z, *(__half2*)&uB.z);
        __half2 p3 = __hadd2(*(__half2*)&uA.w, *(__half2*)&uB.w);
        float2 f;
        f = __half22float2(p0); acc[0] += f.x; acc[1] += f.y;
        f = __half22float2(p1); acc[2] += f.x; acc[3] += f.y;
        f = __half22float2(p2); acc[4] += f.x; acc[5] += f.y;
        f = __half22float2(p3); acc[6] += f.x; acc[7] += f.y;
    }
    for (; j + 2 <= deg; j += 2) {
        int sA = g_csr[rs + j + hl];
        add8f(acc, hp[(size_t)sA * 16 + li]);
    }
    if (j < deg && hl == 0) {
        int sA = g_csr[rs + j];
        add8f(acc, hp[(size_t)sA * 16 + li]);
    }
    #pragma unroll
    for (int k = 0; k < 8; k++)
        acc[k] += __shfl_down_sync(0xFFFFFFFF, acc[k], 16);
    if (hl == 0) {
        float inv = 1.0f / fmaxf((float)deg, 1.0f);
        __half2 o0 = __floats2half2_rn(acc[0] * inv, acc[1] * inv);
        __half2 o1 = __floats2half2_rn(acc[2] * inv, acc[3] * inv);
        __half2 o2 = __floats2half2_rn(acc[4] * inv, acc[5] * inv);
        __half2 o3 = __floats2half2_rn(acc[6] * inv, acc[7] * inv);
        uint4 o = make_uint4(*(unsigned*)&o0, *(unsigned*)&o1,
                             *(unsigned*)&o2, *(unsigned*)&o3);
        ((uint4*)g_hn16)[(size_t)w * 16 + li] = o;
    }
}

// ---------------- K5: bf16-split HMMA GEMM + epilogue + col stats --------
#define ATILE (128 * KP)
#define SM_TOTAL (4 * ATILE * 2)

__device__ __forceinline__ void mma_bf16(float* c, uint32_t a0, uint32_t a1,
                                         uint32_t a2, uint32_t a3,
                                         uint32_t b0, uint32_t b1) {
    asm volatile(
        "mma.sync.aligned.m16n8k16.row.col.f32.bf16.bf16.f32 "
        "{%0,%1,%2,%3}, {%4,%5,%6,%7}, {%8,%9}, {%0,%1,%2,%3};"
        : "+f"(c[0]), "+f"(c[1]), "+f"(c[2]), "+f"(c[3])
        : "r"(a0), "r"(a1), "r"(a2), "r"(a3), "r"(b0), "r"(b1));
}

__global__ void __launch_bounds__(256) k_gemm_mma(const float* __restrict__ h,
                                                  const float* __restrict__ bias,
                                                  const float* __restrict__ snorm) {
    extern __shared__ __align__(16) __nv_bfloat16 smem[];
    __nv_bfloat16* Ahi = smem;
    __nv_bfloat16* Alo = smem + ATILE;
    __nv_bfloat16* Bhi = smem + 2 * ATILE;
    __nv_bfloat16* Blo = smem + 3 * ATILE;
    __shared__ float red[D];
    __shared__ float redq[D];

    const int tid = threadIdx.x;
    const int w   = tid >> 5;
    const int lane = tid & 31;
    const int g = lane >> 2;
    const int t = lane & 3;
    const int row0 = blockIdx.x * 128;

    if (tid < D) { red[tid] = 0.f; redq[tid] = 0.f; }

    const int r = tid >> 1;
    const int half = tid & 1;
    const int grow = row0 + r;
    const bool valid = (grow < N_NODES);

    float acc[16][4];
    #pragma unroll
    for (int nt = 0; nt < 16; nt++)
        #pragma unroll
        for (int c = 0; c < 4; c++) acc[nt][c] = 0.f;

    for (int chunk = 0; chunk < 2; chunk++) {
        __syncthreads();
        // ---- stage A: hi/lo bf16 split ----
        {
            __nv_bfloat16* ah = Ahi + r * KP + half * 64;
            __nv_bfloat16* al = Alo + r * KP + half * 64;
            const float4* rowp = (const float4*)(h + (size_t)grow * D) + half * 16;
            const uint2* rp16 = (const uint2*)(g_hn16 + (size_t)grow * D) + half * 16;
            #pragma unroll
            for (int i = 0; i < 16; i++) {
                float4 v;
                if (chunk == 0) {
                    v = valid ? rowp[i] : make_float4(0.f, 0.f, 0.f, 0.f);
                } else {
                    uint2 u = valid ? rp16[i] : make_uint2(0, 0);
                    float2 f0 = __half22float2(*(__half2*)&u.x);
                    float2 f1 = __half22float2(*(__half2*)&u.y);
                    v = make_float4(f0.x, f0.y, f1.x, f1.y);
                }
                __nv_bfloat162 h0 = __floats2bfloat162_rn(v.x, v.y);
                __nv_bfloat162 h1 = __floats2bfloat162_rn(v.z, v.w);
                float2 f0 = __bfloat1622float2(h0);
                float2 f1 = __bfloat1622float2(h1);
                __nv_bfloat162 l0 = __floats2bfloat162_rn(v.x - f0.x, v.y - f0.y);
                __nv_bfloat162 l1 = __floats2bfloat162_rn(v.z - f1.x, v.w - f1.y);
                *(uint2*)(ah + i * 4) = make_uint2(*(uint32_t*)&h0, *(uint32_t*)&h1);
                *(uint2*)(al + i * 4) = make_uint2(*(uint32_t*)&l0, *(uint32_t*)&l1);
            }
        }
        // ---- copy B hi+lo ----
        {
            const uint4* bsrc = (const uint4*)&g_Bw[chunk][0][0];
            uint4* bdst = (uint4*)Bhi;
            #pragma unroll
            for (int i = 0; i < 17; i++) bdst[tid + i * 256] = bsrc[tid + i * 256];
        }
        __syncthreads();

        // ---- pass 1: (Ahi + Alo) x Bhi ----
        #pragma unroll
        for (int ks = 0; ks < 8; ks++) {
            const int k0 = ks * 16;
            const __nv_bfloat16* ar0 = Ahi + (w * 16 + g) * KP + k0 + t * 2;
            const __nv_bfloat16* ar1 = ar0 + 8 * KP;
            uint32_t ah0 = *(const uint32_t*)ar0;
            uint32_t ah2 = *(const uint32_t*)(ar0 + 8);
            uint32_t ah1 = *(const uint32_t*)ar1;
            uint32_t ah3 = *(const uint32_t*)(ar1 + 8);
            const __nv_bfloat16* al0p = Alo + (w * 16 + g) * KP + k0 + t * 2;
            const __nv_bfloat16* al1p = al0p + 8 * KP;
            uint32_t al0 = *(const uint32_t*)al0p;
            uint32_t al2 = *(const uint32_t*)(al0p + 8);
            uint32_t al1 = *(const uint32_t*)al1p;
            uint32_t al3 = *(const uint32_t*)(al1p + 8);
            #pragma unroll
            for (int nt = 0; nt < 16; nt++) {
                const __nv_bfloat16* br = Bhi + (nt * 8 + g) * KP + k0 + t * 2;
                uint32_t b0 = *(const uint32_t*)br;
                uint32_t b1 = *(const uint32_t*)(br + 8);
                mma_bf16(acc[nt], ah0, ah1, ah2, ah3, b0, b1);
                mma_bf16(acc[nt], al0, al1, al2, al3, b0, b1);
            }
        }
        // ---- pass 2: Ahi x Blo ----
        #pragma unroll
        for (int ks = 0; ks < 8; ks++) {
            const int k0 = ks * 16;
            const __nv_bfloat16* ar0 = Ahi + (w * 16 + g) * KP + k0 + t * 2;
            const __nv_bfloat16* ar1 = ar0 + 8 * KP;
            uint32_t ah0 = *(const uint32_t*)ar0;
            uint32_t ah2 = *(const uint32_t*)(ar0 + 8);
            uint32_t ah1 = *(const uint32_t*)ar1;
            uint32_t ah3 = *(const uint32_t*)(ar1 + 8);
            #pragma unroll
            for (int nt = 0; nt < 16; nt++) {
                const __nv_bfloat16* br = Blo + (nt * 8 + g) * KP + k0 + t * 2;
                uint32_t b0 = *(const uint32_t*)br;
                uint32_t b1 = *(const uint32_t*)(br + 8);
                mma_bf16(acc[nt], ah0, ah1, ah2, ah3, b0, b1);
            }
        }
    }

    // ---- epilogue: bias + relu + snorm -> g_y ; fused column stats ----
    {
        int rowa = row0 + w * 16 + g;
        int rowb = rowa + 8;
        bool va = rowa < N_NODES;
        bool vb = rowb < N_NODES;
        float sna = va ? snorm[rowa] : 0.f;
        float snb = vb ? snorm[rowb] : 0.f;
        #pragma unroll
        for (int nt = 0; nt < 16; nt++) {
            int col = nt * 8 + t * 2;
            float b0 = bias[col], b1 = bias[col + 1];
            float2 oa, ob;
            oa.x = fmaxf(acc[nt][0] + b0, 0.f) * sna;
            oa.y = fmaxf(acc[nt][1] + b1, 0.f) * sna;
            ob.x = fmaxf(acc[nt][2] + b0, 0.f) * snb;
            ob.y = fmaxf(acc[nt][3] + b1, 0.f) * snb;
            if (va) *(float2*)(g_y + (size_t)rowa * D + col) = oa;
            if (vb) *(float2*)(g_y + (size_t)rowb * D + col) = ob;
            float s0 = oa.x + ob.x, s1 = oa.y + ob.y;
            float q0 = oa.x * oa.x + ob.x * ob.x, q1 = oa.y * oa.y + ob.y * ob.y;
            #pragma unroll
            for (int off = 16; off >= 4; off >>= 1) {
                s0 += __shfl_down_sync(0xFFFFFFFF, s0, off);
                s1 += __shfl_down_sync(0xFFFFFFFF, s1, off);
                q0 += __shfl_down_sync(0xFFFFFFFF, q0, off);
                q1 += __shfl_down_sync(0xFFFFFFFF, q1, off);
            }
            if (g == 0) {
                atomicAdd(&red[col], s0);
                atomicAdd(&red[col + 1], s1);
                atomicAdd(&redq[col], q0);
                atomicAdd(&redq[col + 1], q1);
            }
        }
    }
    __syncthreads();
    if (tid < D) {
        atomicAdd(&g_colsum[tid], red[tid]);
        atomicAdd(&g_colsq[tid], redq[tid]);
    }
}

// ---------------- K6: out = h + y*scale + shift ; re-zero g_cnt ----------
__global__ void __launch_bounds__(256) k_final(const float* __restrict__ h,
                                               const float* __restrict__ gamma,
                                               const float* __restrict__ beta,
                                               float* __restrict__ out) {
    __shared__ float ssc[D], ssh[D];
    if (threadIdx.x < D) {
        int c = threadIdx.x;
        float m  = g_colsum[c] * (1.0f / N_NODES);
        float va = g_colsq[c] * (1.0f / N_NODES) - m * m;
        float rs = rsqrtf(va + BN_EPS);
        float sc = rs * gamma[c];
        ssc[c] = sc;
        ssh[c] = beta[c] - m * sc;
    }
    __syncthreads();
    int i = blockIdx.x * blockDim.x + threadIdx.x;
    if (i < N_NODES) g_cnt[i] = 0;     // invariant: cnt zeroed for next run
    if (i >= N_NODES * (D / 4)) return;
    int c4 = i & (D / 4 - 1);
    float4 y  = ((const float4*)g_y)[i];
    float4 hh = ((const float4*)h)[i];
    float4 o;
    o.x = hh.x + y.x * ssc[c4 * 4 + 0] + ssh[c4 * 4 + 0];
    o.y = hh.y + y.y * ssc[c4 * 4 + 1] + ssh[c4 * 4 + 1];
    o.z = hh.z + y.z * ssc[c4 * 4 + 2] + ssh[c4 * 4 + 2];
    o.w = hh.w + y.w * ssc[c4 * 4 + 3] + ssh[c4 * 4 + 3];
    ((float4*)out)[i] = o;
}

// ---------------- launch ----------------
extern "C" void kernel_launch(void* const* d_in, const int* in_sizes, int n_in,
                              void* d_out, int out_size) {
    const float* h      = (const float*)d_in[0];
    const float* snorm  = (const float*)d_in[1];
    const float* Ws     = (const float*)d_in[2];
    const float* Wn     = (const float*)d_in[3];
    const float* bias   = (const float*)d_in[4];
    const float* gamma  = (const float*)d_in[5];
    const float* beta   = (const float*)d_in[6];
    const int*   src    = (const int*)d_in[7];
    const int*   dst    = (const int*)d_in[8];
    float* out = (float*)d_out;

    cudaFuncSetAttribute(k_gemm_mma, cudaFuncAttributeMaxDynamicSharedMemorySize,
                         SM_TOTAL);

    int nd4_blocks = (N_NODES * (D / 4) + 255) / 256;   // 5000
    int edge_blocks = (N_EDGES + 255) / 256;            // 2500
    int gemm_blocks = (N_NODES + 127) / 128;            // 313
    int node_blocks = (N_NODES + 255) / 256;            // 157

    k_prep<<<nd4_blocks, 256>>>(h, dst, Ws, Wn);
    k_scan<<<node_blocks, 256>>>();
    k_fill<<<edge_blocks, 256>>>(src, dst);
    k_gather<<<(N_NODES * 32 + 255) / 256, 256>>>();
    k_gemm_mma<<<gemm_blocks, 256, SM_TOTAL>>>(h, bias, snorm);
    k_final<<<nd4_blocks, 256>>>(h, gamma, beta, out);
}